// round 10
// baseline (speedup 1.0000x reference)
#include <cuda_runtime.h>
#include <math.h>

#define N_RAYS 4096
#define S0     64
#define SMAX   128
#define NIMP   16
#define PB     8      // points per chunk in MLP kernel
#define HID    128

// ---------------- scratch (device globals; no allocation) ----------------
__device__ float g_zA[N_RAYS * SMAX];
__device__ float g_zB[N_RAYS * SMAX];
__device__ float g_sdfA[N_RAYS * SMAX];
__device__ float g_sdfB[N_RAYS * SMAX];
__device__ float g_pts[N_RAYS * SMAX * 3];
__device__ float g_newz[N_RAYS * NIMP];
__device__ float g_newsdf[N_RAYS * NIMP];
__device__ float g_dists[N_RAYS * SMAX];

__device__ __forceinline__ float softplus_f(float x) {
    // logaddexp(x, 0) = max(x,0) + log1p(exp(-|x|))
    return fmaxf(x, 0.f) + log1pf(expf(-fabsf(x)));
}
__device__ __forceinline__ float sigmoid_f(float x) {
    return 1.f / (1.f + expf(-x));
}

// ---------------- init: z linspace + pts ----------------
__global__ void k_init(const float* __restrict__ ro, const float* __restrict__ rd,
                       const float* __restrict__ nearp, const float* __restrict__ farp) {
    int idx = blockIdx.x * blockDim.x + threadIdx.x;   // 0 .. N_RAYS*S0-1
    if (idx >= N_RAYS * S0) return;
    int ray = idx >> 6, s = idx & 63;
    float nr = nearp[ray], fr = farp[ray];
    float z = nr + (fr - nr) * ((float)s * (1.0f / 63.0f));
    g_zA[ray * S0 + s] = z;
    float ox = ro[ray*3], oy = ro[ray*3+1], oz = ro[ray*3+2];
    float dx = rd[ray*3], dy = rd[ray*3+1], dz = rd[ray*3+2];
    g_pts[idx*3+0] = fmaf(dx, z, ox);
    g_pts[idx*3+1] = fmaf(dy, z, oy);
    g_pts[idx*3+2] = fmaf(dz, z, oz);
}

// ---------------- MLP forward (+ optional analytic gradient) ----------------
// block = 128 threads (thread j owns hidden unit j). PB points per chunk.
// Shared layout (floats):
//   W1s[384] b1s[128] W2s[128*129] b2s[128] W3s[128] bufH[PB*128] bufC[PB*128] bufS[PB*128] ptsS[PB*3]
template <bool GRAD>
__global__ __launch_bounds__(128) void k_mlp(
    const float* __restrict__ pts, int npts,
    const float* __restrict__ W1, const float* __restrict__ b1,
    const float* __restrict__ W2, const float* __restrict__ b2,
    const float* __restrict__ W3, const float* __restrict__ b3,
    float* __restrict__ sdf_out, float* __restrict__ grad_out) {

    extern __shared__ float sh[];
    float* W1s = sh;                    // 384
    float* b1s = W1s + 384;             // 128
    float* W2s = b1s + 128;             // 128*129 (pitch 129: conflict-free both ways)
    float* b2s = W2s + 128 * 129;       // 128
    float* W3s = b2s + 128;             // 128
    float* bufH = W3s + 128;            // PB*128  (h1, later g1)
    float* bufC = bufH + PB * 128;      // PB*128  (h2*W3 products, later g2)
    float* bufS = bufC + PB * 128;      // PB*128  (sigmoid(z1), grad only)
    float* ptsS = bufS + PB * 128;      // PB*3

    int tid = threadIdx.x;

    for (int i = tid; i < 384; i += 128) W1s[i] = W1[i];
    b1s[tid] = b1[tid];
    b2s[tid] = b2[tid];
    W3s[tid] = W3[tid];
    for (int i = tid; i < 128 * 128; i += 128) {
        int r = i >> 7, c = i & 127;
        W2s[r * 129 + c] = W2[i];
    }
    float b3v = b3[0];
    __syncthreads();

    int nch = npts / PB;
    for (int ch = blockIdx.x; ch < nch; ch += gridDim.x) {
        int base = ch * PB;
        if (tid < PB * 3) ptsS[tid] = pts[base * 3 + tid];
        __syncthreads();

        // layer 1 — thread j computes unit j for all PB points
        #pragma unroll
        for (int p = 0; p < PB; p++) {
            float z1 = fmaf(ptsS[p*3+2], W1s[256 + tid],
                       fmaf(ptsS[p*3+1], W1s[128 + tid],
                       fmaf(ptsS[p*3+0], W1s[tid], b1s[tid])));
            bufH[p * 128 + tid] = softplus_f(z1);
            if (GRAD) bufS[p * 128 + tid] = sigmoid_f(z1);
        }
        __syncthreads();

        // layer 2: z2[p][j] = b2[j] + sum_k h1[p][k] * W2[k][j]
        float z2[PB];
        #pragma unroll
        for (int p = 0; p < PB; p++) z2[p] = b2s[tid];
        #pragma unroll 4
        for (int k = 0; k < 128; k++) {
            float w = W2s[k * 129 + tid];
            #pragma unroll
            for (int p = 0; p < PB; p++) z2[p] = fmaf(bufH[p * 128 + k], w, z2[p]);
        }

        // products for sdf reduction
        #pragma unroll
        for (int p = 0; p < PB; p++) bufC[p * 128 + tid] = softplus_f(z2[p]) * W3s[tid];
        __syncthreads();

        if (tid < PB) {
            float s = b3v;
            #pragma unroll 8
            for (int k = 0; k < 128; k++) s += bufC[tid * 128 + k];
            sdf_out[base + tid] = s;
        }

        if (GRAD) {
            __syncthreads();
            // g2[p][j] = sigmoid(z2) * W3[j]
            #pragma unroll
            for (int p = 0; p < PB; p++) bufC[p * 128 + tid] = sigmoid_f(z2[p]) * W3s[tid];
            __syncthreads();
            // v[p][i] = sum_j W2[i][j] * g2[p][j]   (transposed read, pitch-129 keeps it conflict-free)
            float g1v[PB];
            #pragma unroll
            for (int p = 0; p < PB; p++) g1v[p] = 0.f;
            #pragma unroll 4
            for (int k = 0; k < 128; k++) {
                float w = W2s[tid * 129 + k];
                #pragma unroll
                for (int p = 0; p < PB; p++) g1v[p] = fmaf(w, bufC[p * 128 + k], g1v[p]);
            }
            // g1 = sigmoid(z1) * v
            #pragma unroll
            for (int p = 0; p < PB; p++) bufH[p * 128 + tid] = bufS[p * 128 + tid] * g1v[p];
            __syncthreads();
            // grad[p][c] = sum_i W1[c][i] * g1[p][i]
            if (tid < PB * 3) {
                int p = tid / 3, c = tid % 3;
                float g = 0.f;
                #pragma unroll 8
                for (int i = 0; i < 128; i++) g = fmaf(W1s[c * 128 + i], bufH[p * 128 + i], g);
                grad_out[(base + p) * 3 + c] = g;
            }
        }
        __syncthreads();
    }
}

// ---------------- upsample: NeuS weights + inverse-CDF sampling (1 thread / ray) ----------------
__global__ void k_upsample(const float* __restrict__ ro, const float* __restrict__ rd,
                           const float* __restrict__ zv, const float* __restrict__ sdfv,
                           int S, float inv_s, int write_pts) {
    int ray = blockIdx.x * blockDim.x + threadIdx.x;
    if (ray >= N_RAYS) return;
    const float* z = zv + ray * S;
    const float* sd = sdfv + ray * S;
    float ox = ro[ray*3], oy = ro[ray*3+1], oz = ro[ray*3+2];
    float dx = rd[ray*3], dy = rd[ray*3+1], dz = rd[ray*3+2];

    // pass 1: total = sum(w + 1e-5)
    float total = 0.f;
    {
        float T = 1.f;
        float z0 = z[0], s0 = sd[0];
        float px = fmaf(dx, z0, ox), py = fmaf(dy, z0, oy), pz = fmaf(dz, z0, oz);
        float r_prev = sqrtf(px*px + py*py + pz*pz);
        float rawprev = 0.f;
        for (int k = 0; k < S - 1; k++) {
            float z1 = z[k+1], s1 = sd[k+1];
            float qx = fmaf(dx, z1, ox), qy = fmaf(dy, z1, oy), qz = fmaf(dz, z1, oz);
            float r_next = sqrtf(qx*qx + qy*qy + qz*qz);
            float inside = (r_prev < 1.f || r_next < 1.f) ? 1.f : 0.f;
            float mid = (s0 + s1) * 0.5f;
            float raw = (s1 - s0) / (z1 - z0 + 1e-5f);
            float cv = fminf(rawprev, raw);
            cv = fminf(fmaxf(cv, -1000.f), 0.f) * inside;
            float dist = z1 - z0;
            float pc = sigmoid_f((mid - cv * dist * 0.5f) * inv_s);
            float nc = sigmoid_f((mid + cv * dist * 0.5f) * inv_s);
            float alpha = (pc - nc + 1e-5f) / (pc + 1e-5f);
            float w = alpha * T;
            T *= (1.f - alpha + 1e-7f);
            total += w + 1e-5f;
            rawprev = raw; z0 = z1; s0 = s1; r_prev = r_next;
        }
    }
    float invtot = 1.f / total;

    // pass 2: streaming CDF + two-pointer inverse CDF (u sorted ascending)
    float* nz = g_newz + ray * NIMP;
    int up = 0;
    {
        float T = 1.f, C = 0.f;
        float z0 = z[0], s0 = sd[0];
        float px = fmaf(dx, z0, ox), py = fmaf(dy, z0, oy), pz = fmaf(dz, z0, oz);
        float r_prev = sqrtf(px*px + py*py + pz*pz);
        float rawprev = 0.f;
        for (int k = 0; k < S - 1; k++) {
            float z1 = z[k+1], s1 = sd[k+1];
            float qx = fmaf(dx, z1, ox), qy = fmaf(dy, z1, oy), qz = fmaf(dz, z1, oz);
            float r_next = sqrtf(qx*qx + qy*qy + qz*qz);
            float inside = (r_prev < 1.f || r_next < 1.f) ? 1.f : 0.f;
            float mid = (s0 + s1) * 0.5f;
            float raw = (s1 - s0) / (z1 - z0 + 1e-5f);
            float cv = fminf(rawprev, raw);
            cv = fminf(fmaxf(cv, -1000.f), 0.f) * inside;
            float dist = z1 - z0;
            float pc = sigmoid_f((mid - cv * dist * 0.5f) * inv_s);
            float nc = sigmoid_f((mid + cv * dist * 0.5f) * inv_s);
            float alpha = (pc - nc + 1e-5f) / (pc + 1e-5f);
            float w = alpha * T;
            T *= (1.f - alpha + 1e-7f);

            float pdf = (w + 1e-5f) * invtot;
            float Cn = C + pdf;
            while (up < NIMP) {
                float u = 0.03125f + 0.0625f * (float)up;
                if (u < Cn) {   // searchsorted 'right': first m with cdf[m] > u
                    float denom = Cn - C;
                    if (denom < 1e-5f) denom = 1.f;
                    float t = (u - C) / denom;
                    nz[up] = fmaf(t, z1 - z0, z0);
                    up++;
                } else break;
            }
            C = Cn;
            rawprev = raw; z0 = z1; s0 = s1; r_prev = r_next;
        }
        float zlast = z[S - 1];
        while (up < NIMP) { nz[up] = zlast; up++; }
    }

    if (write_pts) {
        for (int i = 0; i < NIMP; i++) {
            float zz = nz[i];
            int pi = ray * NIMP + i;
            g_pts[pi*3+0] = fmaf(dx, zz, ox);
            g_pts[pi*3+1] = fmaf(dy, zz, oy);
            g_pts[pi*3+2] = fmaf(dz, zz, oz);
        }
    }
}

// ---------------- stable merge of sorted z_vals (S) with sorted new_z (16) ----------------
__global__ void k_merge(const float* __restrict__ zsrc, const float* __restrict__ ssrc,
                        float* __restrict__ zdst, float* __restrict__ sdst,
                        int S, int with_sdf) {
    int ray = blockIdx.x * blockDim.x + threadIdx.x;
    if (ray >= N_RAYS) return;
    const float* za = zsrc + ray * S;
    const float* sa = ssrc + ray * S;
    const float* zb = g_newz + ray * NIMP;
    const float* sb = g_newsdf + ray * NIMP;
    float* zo = zdst + ray * (S + NIMP);
    float* so = sdst + ray * (S + NIMP);
    int ia = 0, ib = 0;
    for (int o = 0; o < S + NIMP; o++) {
        bool takeA;
        if (ib >= NIMP) takeA = true;
        else if (ia >= S) takeA = false;
        else takeA = (za[ia] <= zb[ib]);   // stable: original entries win ties
        if (takeA) { zo[o] = za[ia]; if (with_sdf) so[o] = sa[ia]; ia++; }
        else       { zo[o] = zb[ib]; if (with_sdf) so[o] = sb[ib]; ib++; }
    }
}

// ---------------- render prep: dists, mid-z points ----------------
__global__ void k_prep(const float* __restrict__ ro, const float* __restrict__ rd) {
    int idx = blockIdx.x * blockDim.x + threadIdx.x;  // 0 .. N_RAYS*SMAX-1
    if (idx >= N_RAYS * SMAX) return;
    int ray = idx >> 7, k = idx & 127;
    const float* z = g_zA + ray * SMAX;
    float zk = z[k];
    float d = (k < 127) ? (z[k+1] - zk) : 0.03125f;   // sample_dist = 2/64
    g_dists[idx] = d;
    float mid = fmaf(d, 0.5f, zk);
    float ox = ro[ray*3], oy = ro[ray*3+1], oz = ro[ray*3+2];
    float dx = rd[ray*3], dy = rd[ray*3+1], dz = rd[ray*3+2];
    g_pts[idx*3+0] = fmaf(dx, mid, ox);
    g_pts[idx*3+1] = fmaf(dy, mid, oy);
    g_pts[idx*3+2] = fmaf(dz, mid, oz);
}

// ---------------- final render: alpha compositing -> depth ----------------
__global__ void k_render(const float* __restrict__ rd, const float* __restrict__ variance,
                         const float* __restrict__ grads, const float* __restrict__ sdfr,
                         float* __restrict__ depths) {
    int ray = blockIdx.x * blockDim.x + threadIdx.x;
    if (ray >= N_RAYS) return;
    float inv_s = expf(10.f * variance[0]);
    inv_s = fminf(fmaxf(inv_s, 1e-6f), 1e6f);
    float dx = rd[ray*3], dy = rd[ray*3+1], dz = rd[ray*3+2];
    const float* z  = g_zA + ray * SMAX;
    const float* sd = sdfr + ray * SMAX;
    const float* dd = g_dists + ray * SMAX;
    float T = 1.f, depth = 0.f;
    for (int k = 0; k < SMAX; k++) {
        int pi = ray * SMAX + k;
        float gx = grads[pi*3], gy = grads[pi*3+1], gz = grads[pi*3+2];
        float tc = dx*gx + dy*gy + dz*gz;
        float ic = -fmaxf(fmaf(-0.5f, tc, 0.5f), 0.f);   // cos_anneal_ratio = 0
        float e = ic * dd[k] * 0.5f;
        float s = sd[k];
        float pc = sigmoid_f((s - e) * inv_s);
        float nc = sigmoid_f((s + e) * inv_s);
        float a = (pc - nc + 1e-5f) / (pc + 1e-5f);
        a = fminf(fmaxf(a, 0.f), 1.f);
        depth = fmaf(a * T, z[k], depth);
        T *= (1.f - a + 1e-7f);
    }
    depths[ray] = depth;
}

// ---------------- launch ----------------
static const int SMEM_FLOATS = 384 + 128 + 128*129 + 128 + 128 + 3*PB*128 + PB*3;
static const int SMEM_BYTES = SMEM_FLOATS * 4;   // 81504 B

extern "C" void kernel_launch(void* const* d_in, const int* in_sizes, int n_in,
                              void* d_out, int out_size) {
    const float* ro  = (const float*)d_in[0];
    const float* rd  = (const float*)d_in[1];
    const float* nr  = (const float*)d_in[2];
    const float* fr  = (const float*)d_in[3];
    const float* W1  = (const float*)d_in[4];
    const float* b1  = (const float*)d_in[5];
    const float* W2  = (const float*)d_in[6];
    const float* b2  = (const float*)d_in[7];
    const float* W3  = (const float*)d_in[8];
    const float* b3  = (const float*)d_in[9];
    const float* var = (const float*)d_in[10];

    float* out    = (float*)d_out;
    float* depths = out;                 // [0, 4096)
    float* grads  = out + N_RAYS;        // [4096, 4096 + 4096*128*3)

    cudaFuncSetAttribute((const void*)k_mlp<false>,
                         cudaFuncAttributeMaxDynamicSharedMemorySize, SMEM_BYTES);
    cudaFuncSetAttribute((const void*)k_mlp<true>,
                         cudaFuncAttributeMaxDynamicSharedMemorySize, SMEM_BYTES);

    float *zA, *zB, *sdfA, *sdfB, *pts, *newsdf;
    cudaGetSymbolAddress((void**)&zA, g_zA);
    cudaGetSymbolAddress((void**)&zB, g_zB);
    cudaGetSymbolAddress((void**)&sdfA, g_sdfA);
    cudaGetSymbolAddress((void**)&sdfB, g_sdfB);
    cudaGetSymbolAddress((void**)&pts, g_pts);
    cudaGetSymbolAddress((void**)&newsdf, g_newsdf);

    const int MLP_GRID = 296;

    // 1. initial samples
    k_init<<<(N_RAYS * S0 + 255) / 256, 256>>>(ro, rd, nr, fr);
    k_mlp<false><<<MLP_GRID, 128, SMEM_BYTES>>>(pts, N_RAYS * S0,
        W1, b1, W2, b2, W3, b3, sdfA, nullptr);

    // 2. hierarchical upsampling (z/sdf ping-pong A->B->A->B->A)
    int S = S0;
    float* zsrc = zA; float* zdst = zB;
    float* ssrc = sdfA; float* sdst = sdfB;
    for (int i = 0; i < 4; i++) {
        float inv_s = 64.f * (float)(1 << i);
        int last = (i == 3);
        k_upsample<<<N_RAYS / 128, 128>>>(ro, rd, zsrc, ssrc, S, inv_s, !last);
        if (!last) {
            k_mlp<false><<<MLP_GRID, 128, SMEM_BYTES>>>(pts, N_RAYS * NIMP,
                W1, b1, W2, b2, W3, b3, newsdf, nullptr);
        }
        k_merge<<<N_RAYS / 128, 128>>>(zsrc, ssrc, zdst, sdst, S, !last);
        S += NIMP;
        float* t;
        t = zsrc; zsrc = zdst; zdst = t;
        t = ssrc; ssrc = sdst; sdst = t;
    }
    // final z is in g_zA (zsrc == zA after 4 swaps)

    // 3. render: mid-z points, MLP forward + gradient, composite
    k_prep<<<(N_RAYS * SMAX + 255) / 256, 256>>>(ro, rd);
    k_mlp<true><<<MLP_GRID, 128, SMEM_BYTES>>>(pts, N_RAYS * SMAX,
        W1, b1, W2, b2, W3, b3, sdfA, grads);
    k_render<<<N_RAYS / 128, 128>>>(rd, var, grads, sdfA, depths);
}

// round 11
// speedup vs baseline: 1.0019x; 1.0019x over previous
#include <cuda_runtime.h>
#include <math.h>

#define N_RAYS 4096
#define S0     64
#define SMAX   128
#define NIMP   16
#define PB     8      // points per chunk in MLP kernel
#define HID    128

// ---------------- scratch (device globals; no allocation) ----------------
__device__ float g_zA[N_RAYS * SMAX];
__device__ float g_zB[N_RAYS * SMAX];
__device__ float g_sdfA[N_RAYS * SMAX];
__device__ float g_sdfB[N_RAYS * SMAX];
__device__ float g_pts[N_RAYS * SMAX * 3];
__device__ float g_newz[N_RAYS * NIMP];
__device__ float g_newsdf[N_RAYS * NIMP];
__device__ float g_dists[N_RAYS * SMAX];

__device__ __forceinline__ float softplus_f(float x) {
    // logaddexp(x, 0) = max(x,0) + log1p(exp(-|x|))
    return fmaxf(x, 0.f) + log1pf(expf(-fabsf(x)));
}
__device__ __forceinline__ float sigmoid_f(float x) {
    return 1.f / (1.f + expf(-x));
}

// ---------------- init: z linspace + pts ----------------
__global__ void k_init(const float* __restrict__ ro, const float* __restrict__ rd,
                       const float* __restrict__ nearp, const float* __restrict__ farp) {
    int idx = blockIdx.x * blockDim.x + threadIdx.x;   // 0 .. N_RAYS*S0-1
    if (idx >= N_RAYS * S0) return;
    int ray = idx >> 6, s = idx & 63;
    float nr = nearp[ray], fr = farp[ray];
    float z = nr + (fr - nr) * ((float)s * (1.0f / 63.0f));
    g_zA[ray * S0 + s] = z;
    float ox = ro[ray*3], oy = ro[ray*3+1], oz = ro[ray*3+2];
    float dx = rd[ray*3], dy = rd[ray*3+1], dz = rd[ray*3+2];
    g_pts[idx*3+0] = fmaf(dx, z, ox);
    g_pts[idx*3+1] = fmaf(dy, z, oy);
    g_pts[idx*3+2] = fmaf(dz, z, oz);
}

// ---------------- MLP forward (+ optional analytic gradient) ----------------
// block = 128 threads (thread j owns hidden unit j). PB points per chunk.
// Shared layout (floats):
//   W1s[384] b1s[128] W2s[128*129] b2s[128] W3s[128] bufH[PB*128] bufC[PB*128] bufS[PB*128] ptsS[PB*3]
template <bool GRAD>
__global__ __launch_bounds__(128) void k_mlp(
    const float* __restrict__ pts, int npts,
    const float* __restrict__ W1, const float* __restrict__ b1,
    const float* __restrict__ W2, const float* __restrict__ b2,
    const float* __restrict__ W3, const float* __restrict__ b3,
    float* __restrict__ sdf_out, float* __restrict__ grad_out) {

    extern __shared__ float sh[];
    float* W1s = sh;                    // 384
    float* b1s = W1s + 384;             // 128
    float* W2s = b1s + 128;             // 128*129 (pitch 129: conflict-free both ways)
    float* b2s = W2s + 128 * 129;       // 128
    float* W3s = b2s + 128;             // 128
    float* bufH = W3s + 128;            // PB*128  (h1, later g1)
    float* bufC = bufH + PB * 128;      // PB*128  (h2*W3 products, later g2)
    float* bufS = bufC + PB * 128;      // PB*128  (sigmoid(z1), grad only)
    float* ptsS = bufS + PB * 128;      // PB*3

    int tid = threadIdx.x;

    for (int i = tid; i < 384; i += 128) W1s[i] = W1[i];
    b1s[tid] = b1[tid];
    b2s[tid] = b2[tid];
    W3s[tid] = W3[tid];
    for (int i = tid; i < 128 * 128; i += 128) {
        int r = i >> 7, c = i & 127;
        W2s[r * 129 + c] = W2[i];
    }
    float b3v = b3[0];
    __syncthreads();

    int nch = npts / PB;
    for (int ch = blockIdx.x; ch < nch; ch += gridDim.x) {
        int base = ch * PB;
        if (tid < PB * 3) ptsS[tid] = pts[base * 3 + tid];
        __syncthreads();

        // layer 1 — thread j computes unit j for all PB points
        #pragma unroll
        for (int p = 0; p < PB; p++) {
            float z1 = fmaf(ptsS[p*3+2], W1s[256 + tid],
                       fmaf(ptsS[p*3+1], W1s[128 + tid],
                       fmaf(ptsS[p*3+0], W1s[tid], b1s[tid])));
            bufH[p * 128 + tid] = softplus_f(z1);
            if (GRAD) bufS[p * 128 + tid] = sigmoid_f(z1);
        }
        __syncthreads();

        // layer 2: z2[p][j] = b2[j] + sum_k h1[p][k] * W2[k][j]
        float z2[PB];
        #pragma unroll
        for (int p = 0; p < PB; p++) z2[p] = b2s[tid];
        #pragma unroll 4
        for (int k = 0; k < 128; k++) {
            float w = W2s[k * 129 + tid];
            #pragma unroll
            for (int p = 0; p < PB; p++) z2[p] = fmaf(bufH[p * 128 + k], w, z2[p]);
        }

        // products for sdf reduction
        #pragma unroll
        for (int p = 0; p < PB; p++) bufC[p * 128 + tid] = softplus_f(z2[p]) * W3s[tid];
        __syncthreads();

        if (tid < PB) {
            float s = b3v;
            #pragma unroll 8
            for (int k = 0; k < 128; k++) s += bufC[tid * 128 + k];
            sdf_out[base + tid] = s;
        }

        if (GRAD) {
            __syncthreads();
            // g2[p][j] = sigmoid(z2) * W3[j]
            #pragma unroll
            for (int p = 0; p < PB; p++) bufC[p * 128 + tid] = sigmoid_f(z2[p]) * W3s[tid];
            __syncthreads();
            // v[p][i] = sum_j W2[i][j] * g2[p][j]   (transposed read, pitch-129 keeps it conflict-free)
            float g1v[PB];
            #pragma unroll
            for (int p = 0; p < PB; p++) g1v[p] = 0.f;
            #pragma unroll 4
            for (int k = 0; k < 128; k++) {
                float w = W2s[tid * 129 + k];
                #pragma unroll
                for (int p = 0; p < PB; p++) g1v[p] = fmaf(w, bufC[p * 128 + k], g1v[p]);
            }
            // g1 = sigmoid(z1) * v
            #pragma unroll
            for (int p = 0; p < PB; p++) bufH[p * 128 + tid] = bufS[p * 128 + tid] * g1v[p];
            __syncthreads();
            // grad[p][c] = sum_i W1[c][i] * g1[p][i]
            if (tid < PB * 3) {
                int p = tid / 3, c = tid % 3;
                float g = 0.f;
                #pragma unroll 8
                for (int i = 0; i < 128; i++) g = fmaf(W1s[c * 128 + i], bufH[p * 128 + i], g);
                grad_out[(base + p) * 3 + c] = g;
            }
        }
        __syncthreads();
    }
}

// ---------------- upsample: NeuS weights + inverse-CDF sampling (1 thread / ray) ----------------
__global__ void k_upsample(const float* __restrict__ ro, const float* __restrict__ rd,
                           const float* __restrict__ zv, const float* __restrict__ sdfv,
                           int S, float inv_s, int write_pts) {
    int ray = blockIdx.x * blockDim.x + threadIdx.x;
    if (ray >= N_RAYS) return;
    const float* z = zv + ray * S;
    const float* sd = sdfv + ray * S;
    float ox = ro[ray*3], oy = ro[ray*3+1], oz = ro[ray*3+2];
    float dx = rd[ray*3], dy = rd[ray*3+1], dz = rd[ray*3+2];

    // pass 1: total = sum(w + 1e-5)
    float total = 0.f;
    {
        float T = 1.f;
        float z0 = z[0], s0 = sd[0];
        float px = fmaf(dx, z0, ox), py = fmaf(dy, z0, oy), pz = fmaf(dz, z0, oz);
        float r_prev = sqrtf(px*px + py*py + pz*pz);
        float rawprev = 0.f;
        for (int k = 0; k < S - 1; k++) {
            float z1 = z[k+1], s1 = sd[k+1];
            float qx = fmaf(dx, z1, ox), qy = fmaf(dy, z1, oy), qz = fmaf(dz, z1, oz);
            float r_next = sqrtf(qx*qx + qy*qy + qz*qz);
            float inside = (r_prev < 1.f || r_next < 1.f) ? 1.f : 0.f;
            float mid = (s0 + s1) * 0.5f;
            float raw = (s1 - s0) / (z1 - z0 + 1e-5f);
            float cv = fminf(rawprev, raw);
            cv = fminf(fmaxf(cv, -1000.f), 0.f) * inside;
            float dist = z1 - z0;
            float pc = sigmoid_f((mid - cv * dist * 0.5f) * inv_s);
            float nc = sigmoid_f((mid + cv * dist * 0.5f) * inv_s);
            float alpha = (pc - nc + 1e-5f) / (pc + 1e-5f);
            float w = alpha * T;
            T *= (1.f - alpha + 1e-7f);
            total += w + 1e-5f;
            rawprev = raw; z0 = z1; s0 = s1; r_prev = r_next;
        }
    }
    float invtot = 1.f / total;

    // pass 2: streaming CDF + two-pointer inverse CDF (u sorted ascending)
    float* nz = g_newz + ray * NIMP;
    int up = 0;
    {
        float T = 1.f, C = 0.f;
        float z0 = z[0], s0 = sd[0];
        float px = fmaf(dx, z0, ox), py = fmaf(dy, z0, oy), pz = fmaf(dz, z0, oz);
        float r_prev = sqrtf(px*px + py*py + pz*pz);
        float rawprev = 0.f;
        for (int k = 0; k < S - 1; k++) {
            float z1 = z[k+1], s1 = sd[k+1];
            float qx = fmaf(dx, z1, ox), qy = fmaf(dy, z1, oy), qz = fmaf(dz, z1, oz);
            float r_next = sqrtf(qx*qx + qy*qy + qz*qz);
            float inside = (r_prev < 1.f || r_next < 1.f) ? 1.f : 0.f;
            float mid = (s0 + s1) * 0.5f;
            float raw = (s1 - s0) / (z1 - z0 + 1e-5f);
            float cv = fminf(rawprev, raw);
            cv = fminf(fmaxf(cv, -1000.f), 0.f) * inside;
            float dist = z1 - z0;
            float pc = sigmoid_f((mid - cv * dist * 0.5f) * inv_s);
            float nc = sigmoid_f((mid + cv * dist * 0.5f) * inv_s);
            float alpha = (pc - nc + 1e-5f) / (pc + 1e-5f);
            float w = alpha * T;
            T *= (1.f - alpha + 1e-7f);

            float pdf = (w + 1e-5f) * invtot;
            float Cn = C + pdf;
            while (up < NIMP) {
                float u = 0.03125f + 0.0625f * (float)up;
                if (u < Cn) {   // searchsorted 'right': first m with cdf[m] > u
                    float denom = Cn - C;
                    if (denom < 1e-5f) denom = 1.f;
                    float t = (u - C) / denom;
                    nz[up] = fmaf(t, z1 - z0, z0);
                    up++;
                } else break;
            }
            C = Cn;
            rawprev = raw; z0 = z1; s0 = s1; r_prev = r_next;
        }
        float zlast = z[S - 1];
        while (up < NIMP) { nz[up] = zlast; up++; }
    }

    if (write_pts) {
        for (int i = 0; i < NIMP; i++) {
            float zz = nz[i];
            int pi = ray * NIMP + i;
            g_pts[pi*3+0] = fmaf(dx, zz, ox);
            g_pts[pi*3+1] = fmaf(dy, zz, oy);
            g_pts[pi*3+2] = fmaf(dz, zz, oz);
        }
    }
}

// ---------------- stable merge of sorted z_vals (S) with sorted new_z (16) ----------------
__global__ void k_merge(const float* __restrict__ zsrc, const float* __restrict__ ssrc,
                        float* __restrict__ zdst, float* __restrict__ sdst,
                        int S, int with_sdf) {
    int ray = blockIdx.x * blockDim.x + threadIdx.x;
    if (ray >= N_RAYS) return;
    const float* za = zsrc + ray * S;
    const float* sa = ssrc + ray * S;
    const float* zb = g_newz + ray * NIMP;
    const float* sb = g_newsdf + ray * NIMP;
    float* zo = zdst + ray * (S + NIMP);
    float* so = sdst + ray * (S + NIMP);
    int ia = 0, ib = 0;
    for (int o = 0; o < S + NIMP; o++) {
        bool takeA;
        if (ib >= NIMP) takeA = true;
        else if (ia >= S) takeA = false;
        else takeA = (za[ia] <= zb[ib]);   // stable: original entries win ties
        if (takeA) { zo[o] = za[ia]; if (with_sdf) so[o] = sa[ia]; ia++; }
        else       { zo[o] = zb[ib]; if (with_sdf) so[o] = sb[ib]; ib++; }
    }
}

// ---------------- render prep: dists, mid-z points ----------------
__global__ void k_prep(const float* __restrict__ ro, const float* __restrict__ rd) {
    int idx = blockIdx.x * blockDim.x + threadIdx.x;  // 0 .. N_RAYS*SMAX-1
    if (idx >= N_RAYS * SMAX) return;
    int ray = idx >> 7, k = idx & 127;
    const float* z = g_zA + ray * SMAX;
    float zk = z[k];
    float d = (k < 127) ? (z[k+1] - zk) : 0.03125f;   // sample_dist = 2/64
    g_dists[idx] = d;
    float mid = fmaf(d, 0.5f, zk);
    float ox = ro[ray*3], oy = ro[ray*3+1], oz = ro[ray*3+2];
    float dx = rd[ray*3], dy = rd[ray*3+1], dz = rd[ray*3+2];
    g_pts[idx*3+0] = fmaf(dx, mid, ox);
    g_pts[idx*3+1] = fmaf(dy, mid, oy);
    g_pts[idx*3+2] = fmaf(dz, mid, oz);
}

// ---------------- final render: alpha compositing -> depth ----------------
__global__ void k_render(const float* __restrict__ rd, const float* __restrict__ variance,
                         const float* __restrict__ grads, const float* __restrict__ sdfr,
                         float* __restrict__ depths) {
    int ray = blockIdx.x * blockDim.x + threadIdx.x;
    if (ray >= N_RAYS) return;
    float inv_s = expf(10.f * variance[0]);
    inv_s = fminf(fmaxf(inv_s, 1e-6f), 1e6f);
    float dx = rd[ray*3], dy = rd[ray*3+1], dz = rd[ray*3+2];
    const float* z  = g_zA + ray * SMAX;
    const float* sd = sdfr + ray * SMAX;
    const float* dd = g_dists + ray * SMAX;
    float T = 1.f, depth = 0.f;
    for (int k = 0; k < SMAX; k++) {
        int pi = ray * SMAX + k;
        float gx = grads[pi*3], gy = grads[pi*3+1], gz = grads[pi*3+2];
        float tc = dx*gx + dy*gy + dz*gz;
        float ic = -fmaxf(fmaf(-0.5f, tc, 0.5f), 0.f);   // cos_anneal_ratio = 0
        float e = ic * dd[k] * 0.5f;
        float s = sd[k];
        float pc = sigmoid_f((s - e) * inv_s);
        float nc = sigmoid_f((s + e) * inv_s);
        float a = (pc - nc + 1e-5f) / (pc + 1e-5f);
        a = fminf(fmaxf(a, 0.f), 1.f);
        depth = fmaf(a * T, z[k], depth);
        T *= (1.f - a + 1e-7f);
    }
    depths[ray] = depth;
}

// ---------------- launch ----------------
static const int SMEM_FLOATS = 384 + 128 + 128*129 + 128 + 128 + 3*PB*128 + PB*3;
static const int SMEM_BYTES = SMEM_FLOATS * 4;   // 81504 B

extern "C" void kernel_launch(void* const* d_in, const int* in_sizes, int n_in,
                              void* d_out, int out_size) {
    const float* ro  = (const float*)d_in[0];
    const float* rd  = (const float*)d_in[1];
    const float* nr  = (const float*)d_in[2];
    const float* fr  = (const float*)d_in[3];
    const float* W1  = (const float*)d_in[4];
    const float* b1  = (const float*)d_in[5];
    const float* W2  = (const float*)d_in[6];
    const float* b2  = (const float*)d_in[7];
    const float* W3  = (const float*)d_in[8];
    const float* b3  = (const float*)d_in[9];
    const float* var = (const float*)d_in[10];

    float* out    = (float*)d_out;
    float* depths = out;                 // [0, 4096)
    float* grads  = out + N_RAYS;        // [4096, 4096 + 4096*128*3)

    cudaFuncSetAttribute((const void*)k_mlp<false>,
                         cudaFuncAttributeMaxDynamicSharedMemorySize, SMEM_BYTES);
    cudaFuncSetAttribute((const void*)k_mlp<true>,
                         cudaFuncAttributeMaxDynamicSharedMemorySize, SMEM_BYTES);

    float *zA, *zB, *sdfA, *sdfB, *pts, *newsdf;
    cudaGetSymbolAddress((void**)&zA, g_zA);
    cudaGetSymbolAddress((void**)&zB, g_zB);
    cudaGetSymbolAddress((void**)&sdfA, g_sdfA);
    cudaGetSymbolAddress((void**)&sdfB, g_sdfB);
    cudaGetSymbolAddress((void**)&pts, g_pts);
    cudaGetSymbolAddress((void**)&newsdf, g_newsdf);

    const int MLP_GRID = 296;

    // 1. initial samples
    k_init<<<(N_RAYS * S0 + 255) / 256, 256>>>(ro, rd, nr, fr);
    k_mlp<false><<<MLP_GRID, 128, SMEM_BYTES>>>(pts, N_RAYS * S0,
        W1, b1, W2, b2, W3, b3, sdfA, nullptr);

    // 2. hierarchical upsampling (z/sdf ping-pong A->B->A->B->A)
    int S = S0;
    float* zsrc = zA; float* zdst = zB;
    float* ssrc = sdfA; float* sdst = sdfB;
    for (int i = 0; i < 4; i++) {
        float inv_s = 64.f * (float)(1 << i);
        int last = (i == 3);
        k_upsample<<<N_RAYS / 128, 128>>>(ro, rd, zsrc, ssrc, S, inv_s, !last);
        if (!last) {
            k_mlp<false><<<MLP_GRID, 128, SMEM_BYTES>>>(pts, N_RAYS * NIMP,
                W1, b1, W2, b2, W3, b3, newsdf, nullptr);
        }
        k_merge<<<N_RAYS / 128, 128>>>(zsrc, ssrc, zdst, sdst, S, !last);
        S += NIMP;
        float* t;
        t = zsrc; zsrc = zdst; zdst = t;
        t = ssrc; ssrc = sdst; sdst = t;
    }
    // final z is in g_zA (zsrc == zA after 4 swaps)

    // 3. render: mid-z points, MLP forward + gradient, composite
    k_prep<<<(N_RAYS * SMAX + 255) / 256, 256>>>(ro, rd);
    k_mlp<true><<<MLP_GRID, 128, SMEM_BYTES>>>(pts, N_RAYS * SMAX,
        W1, b1, W2, b2, W3, b3, sdfA, grads);
    k_render<<<N_RAYS / 128, 128>>>(rd, var, grads, sdfA, depths);
}